// round 1
// baseline (speedup 1.0000x reference)
#include <cuda_runtime.h>
#include <cuda_bf16.h>

#define NMAX 50000
#define DIM 128
#define BN_EPS 1e-5f

// ---------------- device scratch (no allocations allowed) ----------------
__device__ float g_deg[NMAX];
__device__ float g_deg_inv[NMAX];
__device__ float g_dis[NMAX];
__device__ __align__(16) float g_agg[NMAX * DIM];   // scatter target (reused 3x)
__device__ __align__(16) float g_h[NMAX * DIM];     // GEMM output
__device__ __align__(16) float g_z[NMAX * DIM];     // BN+ReLU (+dis) scaled features
__device__ float g_stats[2 * DIM];                  // column sum / sumsq
__device__ float g_bnp[2 * DIM];                    // BN scale / shift

// vector global reduction (sm_90+): 4 floats per op
__device__ __forceinline__ void red_add4(float* p, float4 v) {
    asm volatile("red.global.add.v4.f32 [%0], {%1, %2, %3, %4};"
                 :: "l"(p), "f"(v.x), "f"(v.y), "f"(v.z), "f"(v.w)
                 : "memory");
}

// ---------------- init: zero agg, deg, stats ----------------
__global__ void init_zero_kernel(int n) {
    int i = blockIdx.x * blockDim.x + threadIdx.x;
    int tot = n * (DIM / 4);
    if (i < tot) reinterpret_cast<float4*>(g_agg)[i] = make_float4(0.f, 0.f, 0.f, 0.f);
    if (i < n) g_deg[i] = 0.f;
    if (i < 2 * DIM) g_stats[i] = 0.f;
}

// ---------------- degree ----------------
__global__ void deg_kernel(const int* __restrict__ col, int E) {
    int e = blockIdx.x * blockDim.x + threadIdx.x;
    if (e < E) atomicAdd(&g_deg[col[e]], 1.0f);
}

__global__ void node_prep_kernel(int n) {
    int i = blockIdx.x * blockDim.x + threadIdx.x;
    if (i < n) {
        float d = g_deg[i];
        g_deg_inv[i] = 1.0f / fmaxf(d, 1.0f);   // ClusterGCN 1/deg
        g_dis[i] = rsqrtf(d + 1.0f);            // SGConv D^{-1/2} with self loop
    }
}

// ---------------- edge scatter: one warp per edge, float4 per lane ----------------
// SRC=0: emb_table[x_idx[row]] -> g_agg[col]   (layer 0, raw x)
// SRC=1: g_z[row]              -> g_agg[col]   (SGConv layers, pre-scaled z)
template <int SRC>
__global__ void scatter_kernel(const int* __restrict__ edge, int E,
                               const float* __restrict__ emb,
                               const int* __restrict__ x_idx) {
    int t = blockIdx.x * blockDim.x + threadIdx.x;
    int e = t >> 5;
    if (e >= E) return;
    int lane = t & 31;
    int r = __ldg(edge + e);
    int c = __ldg(edge + E + e);
    const float* src;
    if (SRC == 0) {
        int xr = __ldg(x_idx + r);
        src = emb + (size_t)xr * DIM;
    } else {
        src = g_z + (size_t)r * DIM;
    }
    float4 v = __ldg(reinterpret_cast<const float4*>(src) + lane);
    red_add4(g_agg + (size_t)c * DIM + (lane << 2), v);
}

// ---------------- fused GEMM ----------------
// MODE 0: A[n] = [ deg_inv[n]*g_agg[n] (K 0..127) | emb[x_idx[n]] (K 128..255) ],
//         B = [W_out ; W_root] -> K=256
// MODE 1: A[n] = dis[n]*(g_agg[n] + g_z[n]), B = W_sg -> K=128
// STATS: accumulate column sum/sumsq into g_stats (for BN). BIAS: add bias pre-stats.
// Tile: 64 rows x 128 cols per block, 256 threads, thread computes 4x8 strided.
template <int MODE, bool STATS, bool BIAS>
__global__ __launch_bounds__(256)
void gemm_kernel(const float* __restrict__ emb, const int* __restrict__ x_idx,
                 const float* __restrict__ B1, const float* __restrict__ B2,
                 const float* __restrict__ bias, float* __restrict__ H, int N) {
    constexpr int K = (MODE == 0) ? 256 : 128;
    __shared__ float As[64][17];
    __shared__ float Bs[128][17];
    __shared__ float red[16][128];

    const int tid = threadIdx.x;
    const int tn = tid & 15;   // output cols: tn + 16*j
    const int tm = tid >> 4;   // output rows: tm + 16*i
    const int gm0 = blockIdx.x * 64;

    float acc[4][8];
#pragma unroll
    for (int i = 0; i < 4; i++)
#pragma unroll
        for (int j = 0; j < 8; j++) acc[i][j] = 0.f;

    // tile-load mapping: each thread loads one float4 of A, two float4 of B per chunk
    const int lr = tid >> 2;          // 0..63
    const int lk = (tid & 3) << 2;    // 0,4,8,12

    const int gm_l = gm0 + lr;
    const bool rowok = gm_l < N;
    float rscale = 0.f;
    const float* arow1 = g_agg;
    const float* arow2 = g_agg;
    if (rowok) {
        arow1 = g_agg + (size_t)gm_l * DIM;
        if (MODE == 0) {
            rscale = g_deg_inv[gm_l];
            arow2 = emb + (size_t)__ldg(x_idx + gm_l) * DIM;
        } else {
            rscale = g_dis[gm_l];
            arow2 = g_z + (size_t)gm_l * DIM;
        }
    }

    for (int k0 = 0; k0 < K; k0 += 16) {
        __syncthreads();
        // ---- A tile ----
        float4 av = make_float4(0.f, 0.f, 0.f, 0.f);
        if (rowok) {
            if (MODE == 0) {
                if (k0 < 128) {
                    float4 t = __ldg(reinterpret_cast<const float4*>(arow1 + k0 + lk));
                    av = make_float4(rscale * t.x, rscale * t.y, rscale * t.z, rscale * t.w);
                } else {
                    av = __ldg(reinterpret_cast<const float4*>(arow2 + (k0 - 128) + lk));
                }
            } else {
                float4 t1 = __ldg(reinterpret_cast<const float4*>(arow1 + k0 + lk));
                float4 t2 = __ldg(reinterpret_cast<const float4*>(arow2 + k0 + lk));
                av = make_float4(rscale * (t1.x + t2.x), rscale * (t1.y + t2.y),
                                 rscale * (t1.z + t2.z), rscale * (t1.w + t2.w));
            }
        }
        As[lr][lk + 0] = av.x; As[lr][lk + 1] = av.y;
        As[lr][lk + 2] = av.z; As[lr][lk + 3] = av.w;

        // ---- B tile: Bs[n][kk] = W[n*128 + kw + kk] ----
        const float* Wp;
        int kw;
        if (MODE == 0) { Wp = (k0 < 128) ? B1 : B2; kw = k0 & 127; }
        else           { Wp = B1; kw = k0; }
#pragma unroll
        for (int it = 0; it < 2; it++) {
            int n = lr + 64 * it;
            float4 bv = __ldg(reinterpret_cast<const float4*>(Wp + n * DIM + kw + lk));
            Bs[n][lk + 0] = bv.x; Bs[n][lk + 1] = bv.y;
            Bs[n][lk + 2] = bv.z; Bs[n][lk + 3] = bv.w;
        }
        __syncthreads();

        // ---- inner product ----
#pragma unroll
        for (int kk = 0; kk < 16; kk++) {
            float a[4], b[8];
#pragma unroll
            for (int i = 0; i < 4; i++) a[i] = As[tm + 16 * i][kk];
#pragma unroll
            for (int j = 0; j < 8; j++) b[j] = Bs[tn + 16 * j][kk];
#pragma unroll
            for (int i = 0; i < 4; i++)
#pragma unroll
                for (int j = 0; j < 8; j++)
                    acc[i][j] = fmaf(a[i], b[j], acc[i][j]);
        }
    }

    // ---- epilogue: bias, store, BN stat partials ----
    float bval[8];
#pragma unroll
    for (int j = 0; j < 8; j++) bval[j] = BIAS ? __ldg(bias + tn + 16 * j) : 0.f;

    float psum[8], psq[8];
#pragma unroll
    for (int j = 0; j < 8; j++) { psum[j] = 0.f; psq[j] = 0.f; }

#pragma unroll
    for (int i = 0; i < 4; i++) {
        int gmr = gm0 + tm + 16 * i;
        if (gmr < N) {
#pragma unroll
            for (int j = 0; j < 8; j++) {
                float h = acc[i][j] + bval[j];
                H[(size_t)gmr * DIM + tn + 16 * j] = h;
                if (STATS) { psum[j] += h; psq[j] += h * h; }
            }
        }
    }

    if (STATS) {
#pragma unroll
        for (int pass = 0; pass < 2; pass++) {
            __syncthreads();
#pragma unroll
            for (int j = 0; j < 8; j++)
                red[tm][tn + 16 * j] = pass ? psq[j] : psum[j];
            __syncthreads();
            for (int s = 8; s > 0; s >>= 1) {
                if (tm < s) {
#pragma unroll
                    for (int j = 0; j < 8; j++)
                        red[tm][tn + 16 * j] += red[tm + s][tn + 16 * j];
                }
                __syncthreads();
            }
            if (tm == 0) {
#pragma unroll
                for (int j = 0; j < 8; j++)
                    atomicAdd(&g_stats[pass * DIM + tn + 16 * j], red[0][tn + 16 * j]);
            }
        }
    }
}

// ---------------- BN finalize: scale/shift, reset stats ----------------
__global__ void bn_finalize_kernel(const float* __restrict__ gamma,
                                   const float* __restrict__ beta, int N) {
    int c = threadIdx.x;
    if (c < DIM) {
        float invn = 1.0f / (float)N;
        float mu = g_stats[c] * invn;
        float var = fmaxf(g_stats[DIM + c] * invn - mu * mu, 0.f);
        float scale = __ldg(gamma + c) * rsqrtf(var + BN_EPS);
        g_bnp[c] = scale;
        g_bnp[DIM + c] = __ldg(beta + c) - mu * scale;
        g_stats[c] = 0.f;
        g_stats[DIM + c] = 0.f;
    }
}

// ---------------- BN apply + ReLU + dis-prescale; also zero the scatter buffer ----------------
__global__ void bn_apply_kernel(int N) {
    int i = blockIdx.x * blockDim.x + threadIdx.x;  // float4 index
    int tot = N * (DIM / 4);
    if (i >= tot) return;
    int n = i >> 5;
    int q = i & 31;
    float4 h = reinterpret_cast<const float4*>(g_h)[i];
    float4 sc = reinterpret_cast<const float4*>(g_bnp)[q];
    float4 sh = reinterpret_cast<const float4*>(g_bnp + DIM)[q];
    float d = g_dis[n];
    float4 z;
    z.x = d * fmaxf(fmaf(h.x, sc.x, sh.x), 0.f);
    z.y = d * fmaxf(fmaf(h.y, sc.y, sh.y), 0.f);
    z.z = d * fmaxf(fmaf(h.z, sc.z, sh.z), 0.f);
    z.w = d * fmaxf(fmaf(h.w, sc.w, sh.w), 0.f);
    reinterpret_cast<float4*>(g_z)[i] = z;
    reinterpret_cast<float4*>(g_agg)[i] = make_float4(0.f, 0.f, 0.f, 0.f);
}

// ---------------- launch ----------------
extern "C" void kernel_launch(void* const* d_in, const int* in_sizes, int n_in,
                              void* d_out, int out_size) {
    const int*   x_idx  = (const int*)d_in[0];
    const int*   edge   = (const int*)d_in[1];
    const float* emb    = (const float*)d_in[2];
    const float* W_out  = (const float*)d_in[3];
    const float* W_root = (const float*)d_in[4];
    const float* bn0_g  = (const float*)d_in[5];
    const float* bn0_b  = (const float*)d_in[6];
    const float* W_sg1  = (const float*)d_in[7];
    const float* b_sg1  = (const float*)d_in[8];
    const float* bn1_g  = (const float*)d_in[9];
    const float* bn1_b  = (const float*)d_in[10];
    const float* W_sg2  = (const float*)d_in[11];
    const float* b_sg2  = (const float*)d_in[12];
    float* out = (float*)d_out;

    int N = in_sizes[0];
    int E = in_sizes[1] / 2;

    void* hp = nullptr;
    cudaGetSymbolAddress(&hp, g_h);
    float* Hbuf = (float*)hp;

    const int nbElem = (N * (DIM / 4) + 255) / 256;   // float4 grid over [N,128]
    const int nbEdge = (E * 32 + 255) / 256;          // warp per edge
    const int nbGemm = (N + 63) / 64;

    // degrees + norms
    init_zero_kernel<<<nbElem, 256>>>(N);
    deg_kernel<<<(E + 255) / 256, 256>>>(edge + E, E);
    node_prep_kernel<<<(N + 255) / 256, 256>>>(N);

    // layer 0: ClusterGCN -> BN -> ReLU (z pre-scaled by dis for next layer)
    scatter_kernel<0><<<nbEdge, 256>>>(edge, E, emb, x_idx);
    gemm_kernel<0, true, false><<<nbGemm, 256>>>(emb, x_idx, W_out, W_root, nullptr, Hbuf, N);
    bn_finalize_kernel<<<1, 128>>>(bn0_g, bn0_b, N);
    bn_apply_kernel<<<nbElem, 256>>>(N);

    // layer 1: SGConv -> BN -> ReLU
    scatter_kernel<1><<<nbEdge, 256>>>(edge, E, emb, x_idx);
    gemm_kernel<1, true, true><<<nbGemm, 256>>>(emb, x_idx, W_sg1, nullptr, b_sg1, Hbuf, N);
    bn_finalize_kernel<<<1, 128>>>(bn1_g, bn1_b, N);
    bn_apply_kernel<<<nbElem, 256>>>(N);

    // layer 2: final SGConv -> d_out
    scatter_kernel<1><<<nbEdge, 256>>>(edge, E, emb, x_idx);
    gemm_kernel<1, false, true><<<nbGemm, 256>>>(emb, x_idx, W_sg2, nullptr, b_sg2, out, N);
}

// round 2
// speedup vs baseline: 1.4563x; 1.4563x over previous
#include <cuda_runtime.h>
#include <cuda_bf16.h>

#define NMAX 50000
#define EMAX 600000
#define DIM 128
#define BN_EPS 1e-5f

// ---------------- device scratch (no allocations allowed) ----------------
__device__ int   g_cnt[NMAX];                       // in-degree histogram
__device__ int   g_start[NMAX + 1];                 // CSR offsets (by dest)
__device__ int   g_cursor[NMAX];                    // fill cursors
__device__ int   g_src[EMAX];                       // CSR: source row per slot
__device__ int   g_bsum[64];                        // scan block sums
__device__ int   g_boff[64];                        // scan block offsets (exclusive)
__device__ float g_deg_inv[NMAX];
__device__ float g_dis[NMAX];
__device__ __align__(16) float g_agg[NMAX * DIM];   // gather output (reused 3x)
__device__ __align__(16) float g_h[NMAX * DIM];     // GEMM output
__device__ __align__(16) float g_z[NMAX * DIM];     // BN+ReLU (+dis) scaled features
__device__ float g_stats[2 * DIM];                  // column sum / sumsq
__device__ float g_bnp[2 * DIM];                    // BN scale / shift

// ---------------- packed f32x2 helpers (Blackwell) ----------------
typedef unsigned long long ull;
__device__ __forceinline__ ull pack2(float x, float y) {
    ull r; asm("mov.b64 %0, {%1, %2};" : "=l"(r) : "f"(x), "f"(y)); return r;
}
__device__ __forceinline__ ull ffma2(ull a, ull b, ull c) {
    ull d; asm("fma.rn.f32x2 %0, %1, %2, %3;" : "=l"(d) : "l"(a), "l"(b), "l"(c)); return d;
}
__device__ __forceinline__ float2 unpack2(ull v) {
    float2 f; asm("mov.b64 {%0, %1}, %2;" : "=f"(f.x), "=f"(f.y) : "l"(v)); return f;
}

// ---------------- init: zero histogram + stats ----------------
__global__ void init_zero_kernel(int n) {
    int i = blockIdx.x * blockDim.x + threadIdx.x;
    if (i < n) g_cnt[i] = 0;
    if (i < 2 * DIM) g_stats[i] = 0.f;
}

// ---------------- degree histogram ----------------
__global__ void deg_kernel(const int* __restrict__ col, int E) {
    int e = blockIdx.x * blockDim.x + threadIdx.x;
    if (e < E) atomicAdd(&g_cnt[col[e]], 1);
}

__global__ void node_prep_kernel(int n) {
    int i = blockIdx.x * blockDim.x + threadIdx.x;
    if (i < n) {
        float d = (float)g_cnt[i];
        g_deg_inv[i] = 1.0f / fmaxf(d, 1.0f);   // ClusterGCN 1/deg
        g_dis[i] = rsqrtf(d + 1.0f);            // SGConv D^{-1/2} with self loop
    }
}

// ---------------- 3-kernel exclusive prefix scan (1024 elems/block) ----------------
__global__ void scan1_kernel(int N) {
    __shared__ int sh[256];
    int b = blockIdx.x, t = threadIdx.x;
    int base = b * 1024 + t * 4;
    int s = 0;
#pragma unroll
    for (int q = 0; q < 4; q++) { int idx = base + q; if (idx < N) s += g_cnt[idx]; }
    sh[t] = s; __syncthreads();
    for (int st = 128; st > 0; st >>= 1) {
        if (t < st) sh[t] += sh[t + st];
        __syncthreads();
    }
    if (t == 0) g_bsum[b] = sh[0];
}

__global__ void scan2_kernel(int nb) {
    __shared__ int sh[64];
    int t = threadIdx.x;
    int own = (t < nb) ? g_bsum[t] : 0;
    sh[t] = own; __syncthreads();
    for (int st = 1; st < 64; st <<= 1) {
        int add = (t >= st) ? sh[t - st] : 0;
        __syncthreads();
        sh[t] += add;
        __syncthreads();
    }
    if (t < nb) g_boff[t] = sh[t] - own;   // exclusive
}

__global__ void scan3_kernel(int N, int E) {
    __shared__ int sh[256];
    int b = blockIdx.x, t = threadIdx.x;
    int base = b * 1024 + t * 4;
    int v[4]; int s = 0;
#pragma unroll
    for (int q = 0; q < 4; q++) { int idx = base + q; v[q] = (idx < N) ? g_cnt[idx] : 0; s += v[q]; }
    sh[t] = s; __syncthreads();
    for (int st = 1; st < 256; st <<= 1) {
        int add = (t >= st) ? sh[t - st] : 0;
        __syncthreads();
        sh[t] += add;
        __syncthreads();
    }
    int run = sh[t] - s + g_boff[b];       // exclusive within grid
#pragma unroll
    for (int q = 0; q < 4; q++) {
        int idx = base + q;
        if (idx < N) { g_start[idx] = run; g_cursor[idx] = run; run += v[q]; }
    }
    if (b == 0 && t == 0) g_start[N] = E;
}

// ---------------- fill CSR (atomic cursor; within-bucket order arbitrary) ----------------
__global__ void fill_kernel(const int* __restrict__ edge, int E) {
    int e = blockIdx.x * blockDim.x + threadIdx.x;
    if (e < E) {
        int r = __ldg(edge + e);
        int c = __ldg(edge + E + e);
        int pos = atomicAdd(&g_cursor[c], 1);
        g_src[pos] = r;
    }
}

// ---------------- gather aggregation: one warp per node ----------------
// SRC=0: sum of emb[x_idx[r]] over in-edges;  SRC=1: sum of g_z[r]
template <int SRC>
__global__ void gather_kernel(const float* __restrict__ emb,
                              const int* __restrict__ x_idx, int N) {
    int t = blockIdx.x * blockDim.x + threadIdx.x;
    int n = t >> 5;
    if (n >= N) return;
    int lane = t & 31;
    int s = __ldg(&g_start[n]);
    int e = __ldg(&g_start[n + 1]);
    float4 a0 = make_float4(0.f, 0.f, 0.f, 0.f);
    float4 a1 = make_float4(0.f, 0.f, 0.f, 0.f);
    int i = s;
    for (; i + 2 <= e; i += 2) {
        int r0 = __ldg(&g_src[i]);
        int r1 = __ldg(&g_src[i + 1]);
        const float* p0;
        const float* p1;
        if (SRC == 0) {
            p0 = emb + (size_t)__ldg(x_idx + r0) * DIM;
            p1 = emb + (size_t)__ldg(x_idx + r1) * DIM;
        } else {
            p0 = g_z + (size_t)r0 * DIM;
            p1 = g_z + (size_t)r1 * DIM;
        }
        float4 v0 = __ldg(reinterpret_cast<const float4*>(p0) + lane);
        float4 v1 = __ldg(reinterpret_cast<const float4*>(p1) + lane);
        a0.x += v0.x; a0.y += v0.y; a0.z += v0.z; a0.w += v0.w;
        a1.x += v1.x; a1.y += v1.y; a1.z += v1.z; a1.w += v1.w;
    }
    if (i < e) {
        int r0 = __ldg(&g_src[i]);
        const float* p0 = (SRC == 0) ? emb + (size_t)__ldg(x_idx + r0) * DIM
                                     : g_z + (size_t)r0 * DIM;
        float4 v0 = __ldg(reinterpret_cast<const float4*>(p0) + lane);
        a0.x += v0.x; a0.y += v0.y; a0.z += v0.z; a0.w += v0.w;
    }
    a0.x += a1.x; a0.y += a1.y; a0.z += a1.z; a0.w += a1.w;
    reinterpret_cast<float4*>(g_agg + (size_t)n * DIM)[lane] = a0;
}

// ---------------- fused GEMM with packed f32x2 FMAs ----------------
// MODE 0: A[n] = [ deg_inv[n]*g_agg[n] | emb[x_idx[n]] ], B = [W_out ; W_root], K=256
// MODE 1: A[n] = dis[n]*(g_agg[n] + g_z[n]), B = W_sg, K=128
// Tile 64 rows x 128 cols, 256 threads. Thread owns cols {2*tn+32*jj+{0,1}}, rows {tm+16*i}.
template <int MODE, bool STATS, bool BIAS>
__global__ __launch_bounds__(256)
void gemm_kernel(const float* __restrict__ emb, const int* __restrict__ x_idx,
                 const float* __restrict__ B1, const float* __restrict__ B2,
                 const float* __restrict__ bias, float* __restrict__ H, int N) {
    constexpr int K = (MODE == 0) ? 256 : 128;
    __shared__ float As[64][17];
    __shared__ float Bs[16][130];    // [kk][n], n-contiguous, pad 130 -> conflict-free
    __shared__ float red[16][128];

    const int tid = threadIdx.x;
    const int tn = tid & 15;
    const int tm = tid >> 4;
    const int gm0 = blockIdx.x * 64;

    ull acc[4][4];
#pragma unroll
    for (int i = 0; i < 4; i++)
#pragma unroll
        for (int j = 0; j < 4; j++) acc[i][j] = 0ull;

    const int lr = tid >> 2;          // 0..63
    const int lk = (tid & 3) << 2;    // 0,4,8,12

    const int gm_l = gm0 + lr;
    const bool rowok = gm_l < N;
    float rscale = 0.f;
    const float* arow1 = g_agg;
    const float* arow2 = g_agg;
    if (rowok) {
        arow1 = g_agg + (size_t)gm_l * DIM;
        if (MODE == 0) {
            rscale = g_deg_inv[gm_l];
            arow2 = emb + (size_t)__ldg(x_idx + gm_l) * DIM;
        } else {
            rscale = g_dis[gm_l];
            arow2 = g_z + (size_t)gm_l * DIM;
        }
    }

    for (int k0 = 0; k0 < K; k0 += 16) {
        __syncthreads();
        // ---- A tile ----
        float4 av = make_float4(0.f, 0.f, 0.f, 0.f);
        if (rowok) {
            if (MODE == 0) {
                if (k0 < 128) {
                    float4 t = __ldg(reinterpret_cast<const float4*>(arow1 + k0 + lk));
                    av = make_float4(rscale * t.x, rscale * t.y, rscale * t.z, rscale * t.w);
                } else {
                    av = __ldg(reinterpret_cast<const float4*>(arow2 + (k0 - 128) + lk));
                }
            } else {
                float4 t1 = __ldg(reinterpret_cast<const float4*>(arow1 + k0 + lk));
                float4 t2 = __ldg(reinterpret_cast<const float4*>(arow2 + k0 + lk));
                av = make_float4(rscale * (t1.x + t2.x), rscale * (t1.y + t2.y),
                                 rscale * (t1.z + t2.z), rscale * (t1.w + t2.w));
            }
        }
        As[lr][lk + 0] = av.x; As[lr][lk + 1] = av.y;
        As[lr][lk + 2] = av.z; As[lr][lk + 3] = av.w;

        // ---- B tile (transposed into [kk][n]) ----
        const float* Wp;
        int kw;
        if (MODE == 0) { Wp = (k0 < 128) ? B1 : B2; kw = k0 & 127; }
        else           { Wp = B1; kw = k0; }
#pragma unroll
        for (int it = 0; it < 2; it++) {
            int nn = lr + 64 * it;
            float4 bv = __ldg(reinterpret_cast<const float4*>(Wp + nn * DIM + kw + lk));
            Bs[lk + 0][nn] = bv.x; Bs[lk + 1][nn] = bv.y;
            Bs[lk + 2][nn] = bv.z; Bs[lk + 3][nn] = bv.w;
        }
        __syncthreads();

        // ---- inner product: 16 f32x2 FMAs per kk per thread ----
#pragma unroll
        for (int kk = 0; kk < 16; kk++) {
            const ull* brow = reinterpret_cast<const ull*>(&Bs[kk][0]);
            ull b0 = brow[tn];
            ull b1 = brow[tn + 16];
            ull b2 = brow[tn + 32];
            ull b3 = brow[tn + 48];
#pragma unroll
            for (int i = 0; i < 4; i++) {
                float a = As[tm + 16 * i][kk];
                ull ap = pack2(a, a);
                acc[i][0] = ffma2(ap, b0, acc[i][0]);
                acc[i][1] = ffma2(ap, b1, acc[i][1]);
                acc[i][2] = ffma2(ap, b2, acc[i][2]);
                acc[i][3] = ffma2(ap, b3, acc[i][3]);
            }
        }
    }

    // ---- epilogue: bias, store (float2), BN stat partials ----
    float2 bval[4];
#pragma unroll
    for (int jj = 0; jj < 4; jj++) {
        int col = 2 * tn + 32 * jj;
        bval[jj].x = BIAS ? __ldg(bias + col) : 0.f;
        bval[jj].y = BIAS ? __ldg(bias + col + 1) : 0.f;
    }

    float psum[4][2], psq[4][2];
#pragma unroll
    for (int jj = 0; jj < 4; jj++) {
        psum[jj][0] = psum[jj][1] = 0.f;
        psq[jj][0] = psq[jj][1] = 0.f;
    }

#pragma unroll
    for (int i = 0; i < 4; i++) {
        int gmr = gm0 + tm + 16 * i;
        if (gmr < N) {
#pragma unroll
            for (int jj = 0; jj < 4; jj++) {
                float2 h = unpack2(acc[i][jj]);
                h.x += bval[jj].x; h.y += bval[jj].y;
                int col = 2 * tn + 32 * jj;
                *reinterpret_cast<float2*>(H + (size_t)gmr * DIM + col) = h;
                if (STATS) {
                    psum[jj][0] += h.x; psum[jj][1] += h.y;
                    psq[jj][0] += h.x * h.x; psq[jj][1] += h.y * h.y;
                }
            }
        }
    }

    if (STATS) {
#pragma unroll
        for (int pass = 0; pass < 2; pass++) {
            __syncthreads();
#pragma unroll
            for (int jj = 0; jj < 4; jj++) {
                int col = 2 * tn + 32 * jj;
                red[tm][col]     = pass ? psq[jj][0] : psum[jj][0];
                red[tm][col + 1] = pass ? psq[jj][1] : psum[jj][1];
            }
            __syncthreads();
            for (int s = 8; s > 0; s >>= 1) {
                if (tm < s) {
#pragma unroll
                    for (int jj = 0; jj < 4; jj++) {
                        int col = 2 * tn + 32 * jj;
                        red[tm][col]     += red[tm + s][col];
                        red[tm][col + 1] += red[tm + s][col + 1];
                    }
                }
                __syncthreads();
            }
            if (tm == 0) {
#pragma unroll
                for (int jj = 0; jj < 4; jj++) {
                    int col = 2 * tn + 32 * jj;
                    atomicAdd(&g_stats[pass * DIM + col], red[0][col]);
                    atomicAdd(&g_stats[pass * DIM + col + 1], red[0][col + 1]);
                }
            }
        }
    }
}

// ---------------- BN finalize ----------------
__global__ void bn_finalize_kernel(const float* __restrict__ gamma,
                                   const float* __restrict__ beta, int N) {
    int c = threadIdx.x;
    if (c < DIM) {
        float invn = 1.0f / (float)N;
        float mu = g_stats[c] * invn;
        float var = fmaxf(g_stats[DIM + c] * invn - mu * mu, 0.f);
        float scale = __ldg(gamma + c) * rsqrtf(var + BN_EPS);
        g_bnp[c] = scale;
        g_bnp[DIM + c] = __ldg(beta + c) - mu * scale;
        g_stats[c] = 0.f;
        g_stats[DIM + c] = 0.f;
    }
}

// ---------------- BN apply + ReLU + dis-prescale ----------------
__global__ void bn_apply_kernel(int N) {
    int i = blockIdx.x * blockDim.x + threadIdx.x;  // float4 index
    int tot = N * (DIM / 4);
    if (i >= tot) return;
    int n = i >> 5;
    int q = i & 31;
    float4 h = reinterpret_cast<const float4*>(g_h)[i];
    float4 sc = reinterpret_cast<const float4*>(g_bnp)[q];
    float4 sh = reinterpret_cast<const float4*>(g_bnp + DIM)[q];
    float d = g_dis[n];
    float4 z;
    z.x = d * fmaxf(fmaf(h.x, sc.x, sh.x), 0.f);
    z.y = d * fmaxf(fmaf(h.y, sc.y, sh.y), 0.f);
    z.z = d * fmaxf(fmaf(h.z, sc.z, sh.z), 0.f);
    z.w = d * fmaxf(fmaf(h.w, sc.w, sh.w), 0.f);
    reinterpret_cast<float4*>(g_z)[i] = z;
}

// ---------------- launch ----------------
extern "C" void kernel_launch(void* const* d_in, const int* in_sizes, int n_in,
                              void* d_out, int out_size) {
    const int*   x_idx  = (const int*)d_in[0];
    const int*   edge   = (const int*)d_in[1];
    const float* emb    = (const float*)d_in[2];
    const float* W_out  = (const float*)d_in[3];
    const float* W_root = (const float*)d_in[4];
    const float* bn0_g  = (const float*)d_in[5];
    const float* bn0_b  = (const float*)d_in[6];
    const float* W_sg1  = (const float*)d_in[7];
    const float* b_sg1  = (const float*)d_in[8];
    const float* bn1_g  = (const float*)d_in[9];
    const float* bn1_b  = (const float*)d_in[10];
    const float* W_sg2  = (const float*)d_in[11];
    const float* b_sg2  = (const float*)d_in[12];
    float* out = (float*)d_out;

    int N = in_sizes[0];
    int E = in_sizes[1] / 2;

    void* hp = nullptr;
    cudaGetSymbolAddress(&hp, g_h);
    float* Hbuf = (float*)hp;

    const int nbElem = (N * (DIM / 4) + 255) / 256;
    const int nbNode = (N + 255) / 256;
    const int nbEdgeT = (E + 255) / 256;
    const int nbGath = (N * 32 + 255) / 256;
    const int nbGemm = (N + 63) / 64;
    const int nbScan = (N + 1023) / 1024;

    // CSR build + norms
    init_zero_kernel<<<nbNode, 256>>>(N);
    deg_kernel<<<nbEdgeT, 256>>>(edge + E, E);
    scan1_kernel<<<nbScan, 256>>>(N);
    scan2_kernel<<<1, 64>>>(nbScan);
    scan3_kernel<<<nbScan, 256>>>(N, E);
    node_prep_kernel<<<nbNode, 256>>>(N);
    fill_kernel<<<nbEdgeT, 256>>>(edge, E);

    // layer 0: ClusterGCN -> BN -> ReLU
    gather_kernel<0><<<nbGath, 256>>>(emb, x_idx, N);
    gemm_kernel<0, true, false><<<nbGemm, 256>>>(emb, x_idx, W_out, W_root, nullptr, Hbuf, N);
    bn_finalize_kernel<<<1, 128>>>(bn0_g, bn0_b, N);
    bn_apply_kernel<<<nbElem, 256>>>(N);

    // layer 1: SGConv -> BN -> ReLU
    gather_kernel<1><<<nbGath, 256>>>(emb, x_idx, N);
    gemm_kernel<1, true, true><<<nbGemm, 256>>>(emb, x_idx, W_sg1, nullptr, b_sg1, Hbuf, N);
    bn_finalize_kernel<<<1, 128>>>(bn1_g, bn1_b, N);
    bn_apply_kernel<<<nbElem, 256>>>(N);

    // layer 2: final SGConv -> d_out
    gather_kernel<1><<<nbGath, 256>>>(emb, x_idx, N);
    gemm_kernel<1, false, true><<<nbGemm, 256>>>(emb, x_idx, W_sg2, nullptr, b_sg2, out, N);
}

// round 5
// speedup vs baseline: 2.1239x; 1.4585x over previous
#include <cuda_runtime.h>
#include <cuda_bf16.h>
#include <cstdint>

#define NMAX 50000
#define NPAD 50048          // 391 tiles * 128 rows
#define EMAX 600000
#define DIM 128
#define BN_EPS 1e-5f

// ---------------- device scratch (no allocations allowed) ----------------
__device__ int   g_cnt[NMAX];
__device__ int   g_start[NMAX + 1];
__device__ int   g_cursor[NMAX];
__device__ int   g_src[EMAX];
__device__ int   g_bsum[64];
__device__ int   g_boff[64];
__device__ float g_deg_inv[NMAX];
__device__ float g_dis[NMAX];
__device__ __align__(16) float g_h[NMAX * DIM];      // GEMM output (fp32)
__device__ __align__(16) float g_z[NMAX * DIM];      // dis * relu(bn(h)) for next gather
__device__ float g_stats[2 * DIM];
__device__ float g_bnp[2 * DIM];

// bf16 split images, row-major. A: [NPAD][256 bf16] (=128 u32). Layers 1/2 use cols 0..127.
__device__ __align__(16) uint32_t g_ahi[(size_t)NPAD * 128];
__device__ __align__(16) uint32_t g_alo[(size_t)NPAD * 128];
// B: [sel][128 n][128 k] bf16 = 8192 u32. sel: 0=W_out 1=W_root 2=W_sg1 3=W_sg2
__device__ __align__(16) uint32_t g_bhi[4][8192];
__device__ __align__(16) uint32_t g_blo[4][8192];

// ---------------- helpers ----------------
__device__ __forceinline__ uint32_t smem_u32(const void* p) {
    uint32_t a;
    asm("{ .reg .u64 t; cvta.to.shared.u64 t, %1; cvt.u32.u64 %0, t; }" : "=r"(a) : "l"(p));
    return a;
}
// pack two floats to bf16x2 (low half = first arg)
__device__ __forceinline__ uint32_t bf16pair(float lo, float hi) {
    uint32_t r;
    asm("cvt.rn.bf16x2.f32 %0, %1, %2;" : "=r"(r) : "f"(hi), "f"(lo));
    return r;
}
__device__ __forceinline__ float lo_f(uint32_t p) { return __uint_as_float(p << 16); }
__device__ __forceinline__ float hi_f(uint32_t p) { return __uint_as_float(p & 0xFFFF0000u); }

__device__ __forceinline__ void ldmx4(uint32_t* r, uint32_t addr) {
    asm volatile("ldmatrix.sync.aligned.m8n8.x4.shared.b16 {%0,%1,%2,%3}, [%4];"
                 : "=r"(r[0]), "=r"(r[1]), "=r"(r[2]), "=r"(r[3]) : "r"(addr));
}
__device__ __forceinline__ void ldmx2(uint32_t* r, uint32_t addr) {
    asm volatile("ldmatrix.sync.aligned.m8n8.x2.shared.b16 {%0,%1}, [%2];"
                 : "=r"(r[0]), "=r"(r[1]) : "r"(addr));
}
__device__ __forceinline__ void mma16816(float* d, const uint32_t* a, const uint32_t* b) {
    asm volatile("mma.sync.aligned.m16n8k16.row.col.f32.bf16.bf16.f32 "
                 "{%0,%1,%2,%3}, {%4,%5,%6,%7}, {%8,%9}, {%0,%1,%2,%3};"
                 : "+f"(d[0]), "+f"(d[1]), "+f"(d[2]), "+f"(d[3])
                 : "r"(a[0]), "r"(a[1]), "r"(a[2]), "r"(a[3]), "r"(b[0]), "r"(b[1]));
}

// ---------------- init / degree / norms ----------------
__global__ void init_zero_kernel(int n) {
    int i = blockIdx.x * blockDim.x + threadIdx.x;
    if (i < n) g_cnt[i] = 0;
    if (i < 2 * DIM) g_stats[i] = 0.f;
}
__global__ void deg_kernel(const int* __restrict__ col, int E) {
    int e = blockIdx.x * blockDim.x + threadIdx.x;
    if (e < E) atomicAdd(&g_cnt[col[e]], 1);
}
__global__ void node_prep_kernel(int n) {
    int i = blockIdx.x * blockDim.x + threadIdx.x;
    if (i < n) {
        float d = (float)g_cnt[i];
        g_deg_inv[i] = 1.0f / fmaxf(d, 1.0f);
        g_dis[i] = rsqrtf(d + 1.0f);
    }
}

// ---------------- prefix scan (3 kernels) ----------------
__global__ void scan1_kernel(int N) {
    __shared__ int sh[256];
    int b = blockIdx.x, t = threadIdx.x;
    int base = b * 1024 + t * 4;
    int s = 0;
#pragma unroll
    for (int q = 0; q < 4; q++) { int idx = base + q; if (idx < N) s += g_cnt[idx]; }
    sh[t] = s; __syncthreads();
    for (int st = 128; st > 0; st >>= 1) {
        if (t < st) sh[t] += sh[t + st];
        __syncthreads();
    }
    if (t == 0) g_bsum[b] = sh[0];
}
__global__ void scan2_kernel(int nb) {
    __shared__ int sh[64];
    int t = threadIdx.x;
    int own = (t < nb) ? g_bsum[t] : 0;
    sh[t] = own; __syncthreads();
    for (int st = 1; st < 64; st <<= 1) {
        int add = (t >= st) ? sh[t - st] : 0;
        __syncthreads();
        sh[t] += add;
        __syncthreads();
    }
    if (t < nb) g_boff[t] = sh[t] - own;
}
__global__ void scan3_kernel(int N, int E) {
    __shared__ int sh[256];
    int b = blockIdx.x, t = threadIdx.x;
    int base = b * 1024 + t * 4;
    int v[4]; int s = 0;
#pragma unroll
    for (int q = 0; q < 4; q++) { int idx = base + q; v[q] = (idx < N) ? g_cnt[idx] : 0; s += v[q]; }
    sh[t] = s; __syncthreads();
    for (int st = 1; st < 256; st <<= 1) {
        int add = (t >= st) ? sh[t - st] : 0;
        __syncthreads();
        sh[t] += add;
        __syncthreads();
    }
    int run = sh[t] - s + g_boff[b];
#pragma unroll
    for (int q = 0; q < 4; q++) {
        int idx = base + q;
        if (idx < N) { g_start[idx] = run; g_cursor[idx] = run; run += v[q]; }
    }
    if (b == 0 && t == 0) g_start[N] = E;
}
__global__ void fill_kernel(const int* __restrict__ edge, int E) {
    int e = blockIdx.x * blockDim.x + threadIdx.x;
    if (e < E) {
        int r = __ldg(edge + e);
        int c = __ldg(edge + E + e);
        int pos = atomicAdd(&g_cursor[c], 1);
        g_src[pos] = r;
    }
}

// ---------------- B prep: weights -> bf16 split (row-major) ----------------
__global__ void bprep_kernel(const float* __restrict__ W_out, const float* __restrict__ W_root,
                             const float* __restrict__ W_sg1, const float* __restrict__ W_sg2) {
    int t = blockIdx.x * blockDim.x + threadIdx.x;  // 4 * 8192
    if (t >= 4 * 8192) return;
    int sel = t >> 13;
    int rem = t & 8191;
    int n = rem >> 6;
    int k = (rem & 63) << 1;
    const float* W = (sel == 0) ? W_out : (sel == 1) ? W_root : (sel == 2) ? W_sg1 : W_sg2;
    float x = __ldg(W + n * 128 + k);
    float y = __ldg(W + n * 128 + k + 1);
    uint32_t p = bf16pair(x, y);
    uint32_t q = bf16pair(x - lo_f(p), y - hi_f(p));
    g_bhi[sel][rem] = p;
    g_blo[sel][rem] = q;
}

__device__ __forceinline__ void write_split4(uint32_t* hi, uint32_t* lo, int idx2, float4 v) {
    uint32_t p0 = bf16pair(v.x, v.y);
    uint32_t p1 = bf16pair(v.z, v.w);
    uint32_t q0 = bf16pair(v.x - lo_f(p0), v.y - hi_f(p0));
    uint32_t q1 = bf16pair(v.z - lo_f(p1), v.w - hi_f(p1));
    reinterpret_cast<uint2*>(hi)[idx2] = make_uint2(p0, p1);
    reinterpret_cast<uint2*>(lo)[idx2] = make_uint2(q0, q1);
}

// ---------------- gather: one warp per node; writes bf16 split A rows ----------------
// SRC=0 (layer 0): cols 0..127 = deg_inv[n]*sum(emb[x_idx[r]]); cols 128..255 = emb[x_idx[n]]
// SRC=1 (SGConv):  cols 0..127 = dis[n]*(sum(g_z[r]) + g_z[n]),  z already dis-prescaled
template <int SRC>
__global__ void gather_kernel(const float* __restrict__ emb,
                              const int* __restrict__ x_idx, int N) {
    int t = blockIdx.x * blockDim.x + threadIdx.x;
    int n = t >> 5;
    if (n >= N) return;
    int lane = t & 31;
    int s = __ldg(&g_start[n]);
    int e = __ldg(&g_start[n + 1]);
    float4 a0 = make_float4(0.f, 0.f, 0.f, 0.f);
    float4 a1 = make_float4(0.f, 0.f, 0.f, 0.f);
    int i = s;
    for (; i + 2 <= e; i += 2) {
        int r0 = __ldg(&g_src[i]);
        int r1 = __ldg(&g_src[i + 1]);
        const float* p0;
        const float* p1;
        if (SRC == 0) {
            p0 = emb + (size_t)__ldg(x_idx + r0) * DIM;
            p1 = emb + (size_t)__ldg(x_idx + r1) * DIM;
        } else {
            p0 = g_z + (size_t)r0 * DIM;
            p1 = g_z + (size_t)r1 * DIM;
        }
        float4 v0 = __ldg(reinterpret_cast<const float4*>(p0) + lane);
        float4 v1 = __ldg(reinterpret_cast<const float4*>(p1) + lane);
        a0.x += v0.x; a0.y += v0.y; a0.z += v0.z; a0.w += v0.w;
        a1.x += v1.x; a1.y += v1.y; a1.z += v1.z; a1.w += v1.w;
    }
    if (i < e) {
        int r0 = __ldg(&g_src[i]);
        const float* p0 = (SRC == 0) ? emb + (size_t)__ldg(x_idx + r0) * DIM
                                     : g_z + (size_t)r0 * DIM;
        float4 v0 = __ldg(reinterpret_cast<const float4*>(p0) + lane);
        a0.x += v0.x; a0.y += v0.y; a0.z += v0.z; a0.w += v0.w;
    }
    a0.x += a1.x; a0.y += a1.y; a0.z += a1.z; a0.w += a1.w;

    uint32_t* Ah = g_ahi + (size_t)n * 128;
    uint32_t* Al = g_alo + (size_t)n * 128;

    if (SRC == 0) {
        float sc = g_deg_inv[n];
        write_split4(Ah, Al, lane,
                     make_float4(sc * a0.x, sc * a0.y, sc * a0.z, sc * a0.w));
        const float* pr = emb + (size_t)__ldg(x_idx + n) * DIM;
        float4 vr = __ldg(reinterpret_cast<const float4*>(pr) + lane);
        write_split4(Ah, Al, 32 + lane, vr);
    } else {
        float sc = g_dis[n];
        float4 z = __ldg(reinterpret_cast<const float4*>(g_z + (size_t)n * DIM) + lane);
        write_split4(Ah, Al, lane,
                     make_float4(sc * (a0.x + z.x), sc * (a0.y + z.y),
                                 sc * (a0.z + z.z), sc * (a0.w + z.w)));
    }
}

// ---------------- mma.sync GEMM: 128x128 tile per block, bf16 3-term split ----------------
// smem rows padded to 17 x 16B (272B) -> conflict-free ldmatrix
#define SROW 272
#define OFF_AHI 0
#define OFF_ALO 34816
#define OFF_BHI 69632
#define OFF_BLO 104448
#define SMEM_BYTES 139264

template <int KCHUNKS, bool STATS, bool BIAS>
__global__ __launch_bounds__(256, 1)
void mma_kernel(const float* __restrict__ bias, float* __restrict__ H, int N, int bsel) {
    extern __shared__ __align__(16) char smem[];
    __shared__ float sstats[256];

    const int tid = threadIdx.x;
    const int wid = tid >> 5;
    const int lane = tid & 31;
    const int tile = blockIdx.x;
    const int warpRow = wid & 3;        // 4 row groups of 32
    const int warpCol = wid >> 2;       // 2 col groups of 64

    sstats[tid] = 0.f;

    const uint32_t smemu = smem_u32(smem);

    float acc[2][8][4];
#pragma unroll
    for (int mt = 0; mt < 2; mt++)
#pragma unroll
        for (int nt = 0; nt < 8; nt++)
#pragma unroll
            for (int q = 0; q < 4; q++) acc[mt][nt][q] = 0.f;

    uint32_t aAddr[2][2];   // [mt][hi/lo]
#pragma unroll
    for (int mt = 0; mt < 2; mt++) {
        uint32_t rb = (uint32_t)(warpRow * 32 + mt * 16 + (lane & 15)) * SROW + ((lane >> 4) << 4);
        aAddr[mt][0] = smemu + OFF_AHI + rb;
        aAddr[mt][1] = smemu + OFF_ALO + rb;
    }
    uint32_t bRow = (uint32_t)(warpCol * 64 + (lane & 7)) * SROW + (((lane >> 3) & 1) << 4);
    uint32_t bAddrHi = smemu + OFF_BHI + bRow;
    uint32_t bAddrLo = smemu + OFF_BLO + bRow;

#pragma unroll
    for (int c = 0; c < KCHUNKS; c++) {
        __syncthreads();
        // ---- stage chunk: A_hi/A_lo (tile rows, cols c*128..) + B_hi/B_lo[bsel+c] ----
        {
            const int4* gAh = (const int4*)(g_ahi + ((size_t)tile * 128) * 128) + c * 16;
            const int4* gAl = (const int4*)(g_alo + ((size_t)tile * 128) * 128) + c * 16;
            const int4* gBh = (const int4*)(g_bhi[bsel + c]);
            const int4* gBl = (const int4*)(g_blo[bsel + c]);
            int4* sAh = (int4*)(smem + OFF_AHI);
            int4* sAl = (int4*)(smem + OFF_ALO);
            int4* sBh = (int4*)(smem + OFF_BHI);
            int4* sBl = (int4*)(smem + OFF_BLO);
#pragma unroll
            for (int it = 0; it < 8; it++) {
                int idx = tid + it * 256;           // 0..2047
                int r = idx >> 4;
                int ch = idx & 15;
                int sIdx = r * 17 + ch;
                sAh[sIdx] = __ldg(gAh + r * 32 + ch);   // A global row stride 512B = 32 int4
                sAl[sIdx] = __ldg(gAl + r * 32 + ch);
                sBh[sIdx] = __ldg(gBh + r * 16 + ch);   // B global row stride 256B = 16 int4
                sBl[sIdx] = __ldg(gBl + r * 16 + ch);
            }
        }
        __syncthreads();

#pragma unroll
        for (int ks = 0; ks < 8; ks++) {
            uint32_t ahi[2][4], alo[2][4];
#pragma unroll
            for (int mt = 0; mt < 2; mt++) {
                ldmx4(ahi[mt], aAddr[mt][0] + ks * 32);
                ldmx4(alo[mt], aAddr[mt][1] + ks * 32);
            }
#pragma unroll
            for (int nt = 0; nt < 8; nt++) {
                uint32_t bhi[2], blo[2];
                ldmx2(bhi, bAddrHi + nt * (8 * SROW) + ks * 32);
                ldmx2(blo, bAddrLo + nt * (8 * SROW) + ks * 32);
#pragma unroll
                for (int mt = 0; mt < 2; mt++) {
                    mma16816(acc[mt][nt], ahi[mt], bhi);
                    mma16816(acc[mt][nt], ahi[mt], blo);
                    mma16816(acc[mt][nt], alo[mt], bhi);
                }
            }
        }
    }

    // ---- epilogue: bias + store + BN stats ----
    const int rowbase = tile * 128 + warpRow * 32;
    const int colbase = warpCol * 64;

    float s[8][2], q[8][2];
#pragma unroll
    for (int nt = 0; nt < 8; nt++) { s[nt][0] = s[nt][1] = 0.f; q[nt][0] = q[nt][1] = 0.f; }

#pragma unroll
    for (int mt = 0; mt < 2; mt++) {
        int r0 = rowbase + mt * 16 + (lane >> 2);
        int r1 = r0 + 8;
#pragma unroll
        for (int nt = 0; nt < 8; nt++) {
            int col = colbase + nt * 8 + ((lane & 3) << 1);
            float b0 = BIAS ? __ldg(bias + col) : 0.f;
            float b1 = BIAS ? __ldg(bias + col + 1) : 0.f;
            float v0 = acc[mt][nt][0] + b0;
            float v1 = acc[mt][nt][1] + b1;
            float v2 = acc[mt][nt][2] + b0;
            float v3 = acc[mt][nt][3] + b1;
            if (r0 < N) {
                *(float2*)(H + (size_t)r0 * DIM + col) = make_float2(v0, v1);
                if (STATS) {
                    s[nt][0] += v0; s[nt][1] += v1;
                    q[nt][0] += v0 * v0; q[nt][1] += v1 * v1;
                }
            }
            if (r1 < N) {
                *(float2*)(H + (size_t)r1 * DIM + col) = make_float2(v2, v3);
                if (STATS) {
                    s[nt][0] += v2; s[nt][1] += v3;
                    q[nt][0] += v2 * v2; q[nt][1] += v3 * v3;
                }
            }
        }
    }

    if (STATS) {
#pragma unroll
        for (int nt = 0; nt < 8; nt++) {
#pragma unroll
            for (int p = 0; p < 2; p++) {
                float vs = s[nt][p], vq = q[nt][p];
#pragma unroll
                for (int sh = 4; sh < 32; sh <<= 1) {
                    vs += __shfl_xor_sync(0xFFFFFFFFu, vs, sh);
                    vq += __shfl_xor_sync(0xFFFFFFFFu, vq, sh);
                }
                if (lane < 4) {
                    int col = colbase + nt * 8 + (lane << 1) + p;
                    atomicAdd(&sstats[col], vs);
                    atomicAdd(&sstats[128 + col], vq);
                }
            }
        }
        __syncthreads();
        atomicAdd(&g_stats[tid], sstats[tid]);
    }
}

// ---------------- BN finalize ----------------
__global__ void bn_finalize_kernel(const float* __restrict__ gamma,
                                   const float* __restrict__ beta, int N) {
    int c = threadIdx.x;
    if (c < DIM) {
        float invn = 1.0f / (float)N;
        float mu = g_stats[c] * invn;
        float var = fmaxf(g_stats[DIM + c] * invn - mu * mu, 0.f);
        float scale = __ldg(gamma + c) * rsqrtf(var + BN_EPS);
        g_bnp[c] = scale;
        g_bnp[DIM + c] = __ldg(beta + c) - mu * scale;
        g_stats[c] = 0.f;
        g_stats[DIM + c] = 0.f;
    }
}

// ---------------- BN apply + ReLU + dis-prescale (z = dis * relu(bn(h))) ----------------
__global__ void bn_apply_kernel(int N) {
    int i = blockIdx.x * blockDim.x + threadIdx.x;
    int tot = N * (DIM / 4);
    if (i >= tot) return;
    int n = i >> 5;
    int q = i & 31;
    float4 h = reinterpret_cast<const float4*>(g_h)[i];
    float4 sc = reinterpret_cast<const float4*>(g_bnp)[q];
    float4 sh = reinterpret_cast<const float4*>(g_bnp + DIM)[q];
    float d = g_dis[n];
    float4 z;
    z.x = d * fmaxf(fmaf(h.x, sc.x, sh.x), 0.f);
    z.y = d * fmaxf(fmaf(h.y, sc.y, sh.y), 0.f);
    z.z = d * fmaxf(fmaf(h.z, sc.z, sh.z), 0.f);
    z.w = d * fmaxf(fmaf(h.w, sc.w, sh.w), 0.f);
    reinterpret_cast<float4*>(g_z)[i] = z;
}

// ---------------- launch ----------------
extern "C" void kernel_launch(void* const* d_in, const int* in_sizes, int n_in,
                              void* d_out, int out_size) {
    const int*   x_idx  = (const int*)d_in[0];
    const int*   edge   = (const int*)d_in[1];
    const float* emb    = (const float*)d_in[2];
    const float* W_out  = (const float*)d_in[3];
    const float* W_root = (const float*)d_in[4];
    const float* bn0_g  = (const float*)d_in[5];
    const float* bn0_b  = (const float*)d_in[6];
    const float* W_sg1  = (const float*)d_in[7];
    const float* b_sg1  = (const float*)d_in[8];
    const float* bn1_g  = (const float*)d_in[9];
    const float* bn1_b  = (const float*)d_in[10];
    const float* W_sg2  = (const float*)d_in[11];
    const float* b_sg2  = (const float*)d_in[12];
    float* out = (float*)d_out;

    int N = in_sizes[0];
    int E = in_sizes[1] / 2;

    void* hp = nullptr;
    cudaGetSymbolAddress(&hp, g_h);
    float* Hbuf = (float*)hp;

    cudaFuncSetAttribute(mma_kernel<2, true, false>, cudaFuncAttributeMaxDynamicSharedMemorySize, SMEM_BYTES);
    cudaFuncSetAttribute(mma_kernel<1, true, true>,  cudaFuncAttributeMaxDynamicSharedMemorySize, SMEM_BYTES);
    cudaFuncSetAttribute(mma_kernel<1, false, true>, cudaFuncAttributeMaxDynamicSharedMemorySize, SMEM_BYTES);

    const int nbElem = (N * (DIM / 4) + 255) / 256;
    const int nbNode = (N + 255) / 256;
    const int nbEdgeT = (E + 255) / 256;
    const int nbGath = (N * 32 + 255) / 256;
    const int nbScan = (N + 1023) / 1024;
    const int NT = (N + 127) / 128;

    // CSR build + norms + weight images
    init_zero_kernel<<<nbNode, 256>>>(N);
    deg_kernel<<<nbEdgeT, 256>>>(edge + E, E);
    scan1_kernel<<<nbScan, 256>>>(N);
    scan2_kernel<<<1, 64>>>(nbScan);
    scan3_kernel<<<nbScan, 256>>>(N, E);
    node_prep_kernel<<<nbNode, 256>>>(N);
    fill_kernel<<<nbEdgeT, 256>>>(edge, E);
    bprep_kernel<<<128, 256>>>(W_out, W_root, W_sg1, W_sg2);

    // layer 0: ClusterGCN -> BN -> ReLU
    gather_kernel<0><<<nbGath, 256>>>(emb, x_idx, N);
    mma_kernel<2, true, false><<<NT, 256, SMEM_BYTES>>>(nullptr, Hbuf, N, 0);
    bn_finalize_kernel<<<1, 128>>>(bn0_g, bn0_b, N);
    bn_apply_kernel<<<nbElem, 256>>>(N);

    // layer 1: SGConv -> BN -> ReLU
    gather_kernel<1><<<nbGath, 256>>>(emb, x_idx, N);
    mma_kernel<1, true, true><<<NT, 256, SMEM_BYTES>>>(b_sg1, Hbuf, N, 2);
    bn_finalize_kernel<<<1, 128>>>(bn1_g, bn1_b, N);
    bn_apply_kernel<<<nbElem, 256>>>(N);

    // layer 2: final SGConv -> d_out
    gather_kernel<1><<<nbGath, 256>>>(emb, x_idx, N);
    mma_kernel<1, false, true><<<NT, 256, SMEM_BYTES>>>(b_sg2, out, N, 3);
}